// round 2
// baseline (speedup 1.0000x reference)
#include <cuda_runtime.h>
#include <cstdint>
#include <math.h>

#define NN 2708

// ---------------------------------------------------------------------------
// Threefry-2x32, 20 rounds, key = jax.random.key(42) -> (k0, k1) = (0, 42).
// Partitionable counter mode (JAX >= 0.4.30 default):
//   element idx: counter = (hi32(idx)=0, lo32(idx)=idx), output = lane0 ^ lane1
// ---------------------------------------------------------------------------
__device__ __forceinline__ uint32_t rotl32(uint32_t v, int s) {
    return (v << s) | (v >> (32 - s));
}

__device__ __forceinline__ void tf_mix(uint32_t& x0, uint32_t& x1, int r) {
    x0 += x1;
    x1 = rotl32(x1, r);
    x1 ^= x0;
}

__device__ __forceinline__ uint32_t threefry_bits_key42(uint32_t idx) {
    const uint32_t ks0 = 0u;
    const uint32_t ks1 = 42u;
    const uint32_t ks2 = 0x1BD11BDAu ^ 42u;  // k0 ^ k1 ^ parity

    uint32_t x0 = 0u;     // hi32 of uint64 counter (always 0 for idx < 2^32)
    uint32_t x1 = idx;    // lo32

    x0 += ks0; x1 += ks1;
    tf_mix(x0, x1, 13); tf_mix(x0, x1, 15); tf_mix(x0, x1, 26); tf_mix(x0, x1, 6);
    x0 += ks1; x1 += ks2 + 1u;
    tf_mix(x0, x1, 17); tf_mix(x0, x1, 29); tf_mix(x0, x1, 16); tf_mix(x0, x1, 24);
    x0 += ks2; x1 += ks0 + 2u;
    tf_mix(x0, x1, 13); tf_mix(x0, x1, 15); tf_mix(x0, x1, 26); tf_mix(x0, x1, 6);
    x0 += ks0; x1 += ks1 + 3u;
    tf_mix(x0, x1, 17); tf_mix(x0, x1, 29); tf_mix(x0, x1, 16); tf_mix(x0, x1, 24);
    x0 += ks1; x1 += ks2 + 4u;
    tf_mix(x0, x1, 13); tf_mix(x0, x1, 15); tf_mix(x0, x1, 26); tf_mix(x0, x1, 6);
    x0 += ks2; x1 += ks0 + 5u;

    return x0 ^ x1;  // 32-bit partitionable fold
}

__device__ __forceinline__ float jax_uniform_at(uint32_t idx) {
    uint32_t bits = threefry_bits_key42(idx);
    return __uint_as_float((bits >> 9) | 0x3f800000u) - 1.0f;
}

// ---------------------------------------------------------------------------
// out[i,j] = adj[i,j]                                   if cluster[i] != cluster[j]
//          = 0                                          if i == j (same cluster)
//          = bernoulli(key42, sigmoid(mask))[max,min]   (1.0 / 0.0) otherwise
// ---------------------------------------------------------------------------
__global__ void __launch_bounds__(256) mask_kernel(
    const float* __restrict__ mask,
    const float* __restrict__ adj,
    const int*   __restrict__ cid,
    float*       __restrict__ out)
{
    int j = blockIdx.x * 256 + threadIdx.x;
    int i = blockIdx.y;
    if (j >= NN) return;

    int ci = __ldg(&cid[i]);
    int cj = __ldg(&cid[j]);
    size_t pos = (size_t)i * NN + (size_t)j;

    float result;
    if (ci != cj) {
        result = __ldg(&adj[pos]);
    } else if (i == j) {
        result = 0.0f;
    } else {
        int r = i > j ? i : j;   // lower-triangle row (max)
        int c = i > j ? j : i;   // lower-triangle col (min)
        uint32_t idx = (uint32_t)r * (uint32_t)NN + (uint32_t)c;

        float u = jax_uniform_at(idx);
        float m = __ldg(&mask[(size_t)r * NN + c]);

        float a_sig = 1.0f / (1.0f + expf(-m));
        // Boundary refinement: if the fp32 sigmoid could be close enough to u
        // that rounding decides the draw, recompute correctly rounded in fp64.
        // Triggers on ~O(100) of 7.3M elements — negligible cost.
        if (fabsf(u - a_sig) < 1e-4f) {
            a_sig = (float)(1.0 / (1.0 + exp(-(double)m)));
        }
        result = (u < a_sig) ? 1.0f : 0.0f;
    }
    out[pos] = result;
}

extern "C" void kernel_launch(void* const* d_in, const int* in_sizes, int n_in,
                              void* d_out, int out_size) {
    const float* mask = (const float*)d_in[0];
    const float* adj  = (const float*)d_in[1];
    const int*   cid  = (const int*)d_in[2];
    float*       out  = (float*)d_out;

    dim3 block(256, 1, 1);
    dim3 grid((NN + 255) / 256, NN, 1);
    mask_kernel<<<grid, block>>>(mask, adj, cid, out);
}

// round 3
// speedup vs baseline: 2.0614x; 2.0614x over previous
#include <cuda_runtime.h>
#include <cstdint>
#include <math.h>

#define NN 2708
#define NC 7
#define W4 (NN / 4)   // 677 float4 per row (2708 = 4*677)

// ---------------------------------------------------------------------------
// Scratch (no allocations allowed -> __device__ globals)
// ---------------------------------------------------------------------------
__device__ int g_nodes[NC][NN];     // node ids per cluster (order arbitrary)
__device__ int g_pair_off[NC + 1];  // prefix sums of per-cluster pair counts

// ---------------------------------------------------------------------------
// Threefry-2x32, 20 rounds, key = (0, 42), partitionable counter mode:
//   counter = (0, idx), output = lane0 ^ lane1.  (verified bit-exact in R2)
// ---------------------------------------------------------------------------
__device__ __forceinline__ uint32_t rotl32(uint32_t v, int s) {
    return (v << s) | (v >> (32 - s));
}

__device__ __forceinline__ void tf_mix(uint32_t& x0, uint32_t& x1, int r) {
    x0 += x1;
    x1 = rotl32(x1, r);
    x1 ^= x0;
}

__device__ __forceinline__ uint32_t threefry_bits_key42(uint32_t idx) {
    const uint32_t ks0 = 0u;
    const uint32_t ks1 = 42u;
    const uint32_t ks2 = 0x1BD11BDAu ^ 42u;

    uint32_t x0 = 0u;
    uint32_t x1 = idx;

    x0 += ks0; x1 += ks1;
    tf_mix(x0, x1, 13); tf_mix(x0, x1, 15); tf_mix(x0, x1, 26); tf_mix(x0, x1, 6);
    x0 += ks1; x1 += ks2 + 1u;
    tf_mix(x0, x1, 17); tf_mix(x0, x1, 29); tf_mix(x0, x1, 16); tf_mix(x0, x1, 24);
    x0 += ks2; x1 += ks0 + 2u;
    tf_mix(x0, x1, 13); tf_mix(x0, x1, 15); tf_mix(x0, x1, 26); tf_mix(x0, x1, 6);
    x0 += ks0; x1 += ks1 + 3u;
    tf_mix(x0, x1, 17); tf_mix(x0, x1, 29); tf_mix(x0, x1, 16); tf_mix(x0, x1, 24);
    x0 += ks1; x1 += ks2 + 4u;
    tf_mix(x0, x1, 13); tf_mix(x0, x1, 15); tf_mix(x0, x1, 26); tf_mix(x0, x1, 6);
    x0 += ks2; x1 += ks0 + 5u;

    return x0 ^ x1;
}

__device__ __forceinline__ float jax_uniform_at(uint32_t idx) {
    uint32_t bits = threefry_bits_key42(idx);
    return __uint_as_float((bits >> 9) | 0x3f800000u) - 1.0f;
}

// ---------------------------------------------------------------------------
// Kernel 1: bucket nodes by cluster, build pair-count prefix.
// ---------------------------------------------------------------------------
__global__ void setup_kernel(const int* __restrict__ cid) {
    __shared__ int s_cnt[NC];
    int tid = threadIdx.x;
    if (tid < NC) s_cnt[tid] = 0;
    __syncthreads();
    for (int n = tid; n < NN; n += blockDim.x) {
        int c = cid[n];
        int pos = atomicAdd(&s_cnt[c], 1);
        g_nodes[c][pos] = n;
    }
    __syncthreads();
    if (tid == 0) {
        int off = 0;
        for (int k = 0; k < NC; k++) {
            int s = s_cnt[k];
            g_pair_off[k] = off;
            off += s * (s - 1) / 2;
        }
        g_pair_off[NC] = off;
    }
}

// ---------------------------------------------------------------------------
// Kernel 2: base pass, float4 coalesced:
//   out[i,j] = (cid[i] != cid[j]) ? adj[i,j] : 0
// (covers diagonal = 0 and all non-firing intra entries = 0)
// ---------------------------------------------------------------------------
__global__ void __launch_bounds__(256) base_kernel(
    const float* __restrict__ adj,
    const int*   __restrict__ cid,
    float*       __restrict__ out)
{
    int t = blockIdx.x * 256 + threadIdx.x;   // float4 index
    if (t >= W4 * NN) return;
    int i  = t / W4;
    int j4 = (t - i * W4) * 4;
    int ci = __ldg(&cid[i]);

    size_t base = (size_t)i * NN + j4;
    float4 a = *reinterpret_cast<const float4*>(adj + base);
    int4  cj = *reinterpret_cast<const int4*>(cid + j4);

    float4 r;
    r.x = (cj.x != ci) ? a.x : 0.0f;
    r.y = (cj.y != ci) ? a.y : 0.0f;
    r.z = (cj.z != ci) ? a.z : 0.0f;
    r.w = (cj.w != ci) ? a.w : 0.0f;
    *reinterpret_cast<float4*>(out + base) = r;
}

// ---------------------------------------------------------------------------
// Kernel 3: compact intra-cluster pair pass. One thread per unordered pair.
// Writes 1.0 to both symmetric positions iff the Bernoulli draw fires.
// ---------------------------------------------------------------------------
__global__ void __launch_bounds__(256) pair_kernel(
    const float* __restrict__ mask,
    float*       __restrict__ out)
{
    int total  = g_pair_off[NC];
    int stride = gridDim.x * blockDim.x;
    for (int p = blockIdx.x * 256 + threadIdx.x; p < total; p += stride) {
        // locate cluster (7-entry scan)
        int k = 0;
        #pragma unroll
        for (int kk = 1; kk < NC; kk++)
            if (p >= g_pair_off[kk]) k = kk;
        int q = p - g_pair_off[k];

        // triangular decode: q = row*(row-1)/2 + col, 0 <= col < row
        int row = (int)((1.0f + sqrtf(8.0f * (float)q + 1.0f)) * 0.5f);
        while (row * (row - 1) / 2 > q) row--;
        while ((row + 1) * row / 2 <= q) row++;
        int col = q - row * (row - 1) / 2;

        int na = g_nodes[k][row];
        int nb = g_nodes[k][col];
        int r = na > nb ? na : nb;
        int c = na > nb ? nb : na;

        uint32_t idx = (uint32_t)r * (uint32_t)NN + (uint32_t)c;
        float u = jax_uniform_at(idx);
        float m = __ldg(&mask[idx]);

        float a_sig = 1.0f / (1.0f + expf(-m));
        if (fabsf(u - a_sig) < 1e-4f) {
            a_sig = (float)(1.0 / (1.0 + exp(-(double)m)));
        }
        if (u < a_sig) {
            out[(size_t)r * NN + c] = 1.0f;
            out[(size_t)c * NN + r] = 1.0f;
        }
    }
}

extern "C" void kernel_launch(void* const* d_in, const int* in_sizes, int n_in,
                              void* d_out, int out_size) {
    const float* mask = (const float*)d_in[0];
    const float* adj  = (const float*)d_in[1];
    const int*   cid  = (const int*)d_in[2];
    float*       out  = (float*)d_out;

    setup_kernel<<<1, 256>>>(cid);

    int base_threads = W4 * NN;                       // 1,833,316
    base_kernel<<<(base_threads + 255) / 256, 256>>>(adj, cid, out);

    pair_kernel<<<2048, 256>>>(mask, out);            // grid-stride, ~524k pairs
}

// round 5
// speedup vs baseline: 2.1617x; 1.0487x over previous
#include <cuda_runtime.h>
#include <cstdint>
#include <math.h>

#define NN 2708
#define NC 7
#define W4 (NN / 4)   // 677 float4 per row (2708 = 4*677)

// ---------------------------------------------------------------------------
// Scratch (no allocations allowed -> __device__ globals)
// ---------------------------------------------------------------------------
__device__ int g_nodes[NC][NN];   // node ids per cluster, ascending order
__device__ int g_csize[NC];       // cluster sizes

// ---------------------------------------------------------------------------
// Threefry-2x32, 20 rounds, key = (0, 42), partitionable counter mode:
//   counter = (0, idx), output = lane0 ^ lane1.  (verified bit-exact R2/R3)
// ---------------------------------------------------------------------------
__device__ __forceinline__ uint32_t rotl32(uint32_t v, int s) {
    return (v << s) | (v >> (32 - s));
}

__device__ __forceinline__ void tf_mix(uint32_t& x0, uint32_t& x1, int r) {
    x0 += x1;
    x1 = rotl32(x1, r);
    x1 ^= x0;
}

__device__ __forceinline__ uint32_t threefry_bits_key42(uint32_t idx) {
    const uint32_t ks0 = 0u;
    const uint32_t ks1 = 42u;
    const uint32_t ks2 = 0x1BD11BDAu ^ 42u;

    uint32_t x0 = 0u;
    uint32_t x1 = idx;

    x0 += ks0; x1 += ks1;
    tf_mix(x0, x1, 13); tf_mix(x0, x1, 15); tf_mix(x0, x1, 26); tf_mix(x0, x1, 6);
    x0 += ks1; x1 += ks2 + 1u;
    tf_mix(x0, x1, 17); tf_mix(x0, x1, 29); tf_mix(x0, x1, 16); tf_mix(x0, x1, 24);
    x0 += ks2; x1 += ks0 + 2u;
    tf_mix(x0, x1, 13); tf_mix(x0, x1, 15); tf_mix(x0, x1, 26); tf_mix(x0, x1, 6);
    x0 += ks0; x1 += ks1 + 3u;
    tf_mix(x0, x1, 17); tf_mix(x0, x1, 29); tf_mix(x0, x1, 16); tf_mix(x0, x1, 24);
    x0 += ks1; x1 += ks2 + 4u;
    tf_mix(x0, x1, 13); tf_mix(x0, x1, 15); tf_mix(x0, x1, 26); tf_mix(x0, x1, 6);
    x0 += ks2; x1 += ks0 + 5u;

    return x0 ^ x1;
}

__device__ __forceinline__ float jax_uniform_at(uint32_t idx) {
    uint32_t bits = threefry_bits_key42(idx);
    return __uint_as_float((bits >> 9) | 0x3f800000u) - 1.0f;
}

// ---------------------------------------------------------------------------
// Kernel 1 (fused): block 0 does ballot-based cluster bucketing (warp w
// compacts cluster w, ascending node order); blocks [1, NB_BASE] stream
//   out[i,j] = (cid[i] != cid[j]) ? adj[i,j] : 0
// Setup runs in wave 1 and is fully hidden under the streaming pass.
// ---------------------------------------------------------------------------
#define NB_BASE ((W4 * NN + 255) / 256)   // 7162

__global__ void __launch_bounds__(256) base_setup_kernel(
    const float* __restrict__ adj,
    const int*   __restrict__ cid,
    float*       __restrict__ out)
{
    if (blockIdx.x == 0) {
        // ---- setup: warp-per-cluster ballot compaction ----
        int w    = threadIdx.x >> 5;
        int lane = threadIdx.x & 31;
        if (w < NC) {
            int cnt = 0;
            for (int b = 0; b < NN; b += 32) {
                int n = b + lane;
                int c = (n < NN) ? __ldg(&cid[n]) : -1;
                unsigned m = __ballot_sync(0xffffffffu, c == w);
                if (c == w) {
                    int pos = cnt + __popc(m & ((1u << lane) - 1u));
                    g_nodes[w][pos] = n;
                }
                cnt += __popc(m);
            }
            if (lane == 0) g_csize[w] = cnt;
        }
        return;
    }

    // ---- base streaming pass (float4) ----
    int t = (blockIdx.x - 1) * 256 + threadIdx.x;
    if (t >= W4 * NN) return;
    int i  = t / W4;
    int j4 = (t - i * W4) * 4;
    int ci = __ldg(&cid[i]);

    size_t base = (size_t)i * NN + j4;
    float4 a = *reinterpret_cast<const float4*>(adj + base);
    int4  cj = *reinterpret_cast<const int4*>(cid + j4);

    float4 r;
    r.x = (cj.x != ci) ? a.x : 0.0f;
    r.y = (cj.y != ci) ? a.y : 0.0f;
    r.z = (cj.z != ci) ? a.z : 0.0f;
    r.w = (cj.w != ci) ? a.w : 0.0f;
    *reinterpret_cast<float4*>(out + base) = r;
}

// ---------------------------------------------------------------------------
// Kernel 2: compact intra-cluster pair pass. One thread per unordered pair,
// grid-stride. Writes 1.0 to both symmetric positions iff the draw fires.
// ---------------------------------------------------------------------------
__global__ void __launch_bounds__(256) pair_kernel(
    const float* __restrict__ mask,
    float*       __restrict__ out)
{
    // per-thread prefix of pair counts (7 values, registers)
    int off[NC + 1];
    off[0] = 0;
    #pragma unroll
    for (int k = 0; k < NC; k++) {
        int s = __ldg(&g_csize[k]);
        off[k + 1] = off[k] + (s * (s - 1)) / 2;
    }
    int total  = off[NC];
    int stride = gridDim.x * blockDim.x;

    for (int p = blockIdx.x * 256 + threadIdx.x; p < total; p += stride) {
        // locate cluster
        int k = 0;
        #pragma unroll
        for (int kk = 1; kk < NC; kk++)
            if (p >= off[kk]) k = kk;
        int q = p - off[k];

        // triangular decode: q = row*(row-1)/2 + col, 0 <= col < row
        int row = (int)((1.0f + sqrtf(8.0f * (float)q + 1.0f)) * 0.5f);
        int tri = row * (row - 1) / 2;
        while (tri > q)            { row--; tri -= row; }
        while (tri + row <= q)     { tri += row; row++; }
        int col = q - tri;

        int na = g_nodes[k][row];   // ascending order -> na > nb
        int nb = g_nodes[k][col];
        int r = na > nb ? na : nb;
        int c = na > nb ? nb : na;

        uint32_t idx = (uint32_t)r * (uint32_t)NN + (uint32_t)c;
        float u = jax_uniform_at(idx);
        float m = __ldg(&mask[idx]);

        float a_sig = 1.0f / (1.0f + expf(-m));
        if (fabsf(u - a_sig) < 1e-4f) {
            a_sig = (float)(1.0 / (1.0 + exp(-(double)m)));
        }
        if (u < a_sig) {
            out[(size_t)r * NN + c] = 1.0f;
            out[(size_t)c * NN + r] = 1.0f;
        }
    }
}

extern "C" void kernel_launch(void* const* d_in, const int* in_sizes, int n_in,
                              void* d_out, int out_size) {
    const float* mask = (const float*)d_in[0];
    const float* adj  = (const float*)d_in[1];
    const int*   cid  = (const int*)d_in[2];
    float*       out  = (float*)d_out;

    base_setup_kernel<<<NB_BASE + 1, 256>>>(adj, cid, out);
    pair_kernel<<<1184, 256>>>(mask, out);   // ~303k threads, ~524k pairs
}